// round 14
// baseline (speedup 1.0000x reference)
#include <cuda_runtime.h>
#include <math.h>
#include <stdint.h>

// Problem constants
#define Bb      2
#define Nn      2048
#define Cc      1024
#define Hh      16
#define Dd      64
#define MROWS   (Bb * Nn)      // 4096
#define THREEC  (3 * Cc)       // 3072
#define LOGMAX  4.6051701859880914f  // ln(100)
#define MASKNEG (-1e30f)

// ---------------------------------------------------------------------------
// Scratch
// ---------------------------------------------------------------------------
__device__ float g_qkv[(size_t)MROWS * THREEC];          // 50 MB
__device__ float g_att[(size_t)MROWS * Cc];              // 16 MB

// ---------------------------------------------------------------------------
// tf32 mma.sync helpers (sm_80+ PTX — safe under compute_103 family target)
// ---------------------------------------------------------------------------
__device__ __forceinline__ uint32_t f2t(float x) {
    uint32_t u;
    asm("cvt.rna.tf32.f32 %0, %1;" : "=r"(u) : "f"(x));
    return u;
}

__device__ __forceinline__ void mma8(float* d, const uint32_t* a, const uint32_t* b) {
    asm volatile(
        "mma.sync.aligned.m16n8k8.row.col.f32.tf32.tf32.f32 "
        "{%0,%1,%2,%3}, {%4,%5,%6,%7}, {%8,%9}, {%0,%1,%2,%3};"
        : "+f"(d[0]), "+f"(d[1]), "+f"(d[2]), "+f"(d[3])
        : "r"(a[0]), "r"(a[1]), "r"(a[2]), "r"(a[3]), "r"(b[0]), "r"(b[1]));
}
// Frag maps (g = lane>>2, tg = lane&3):
//   A: a0=(g,tg) a1=(g+8,tg) a2=(g,tg+4) a3=(g+8,tg+4)      [row, k]
//   B: b0=(k=tg,n=g) b1=(k=tg+4,n=g)                         [k, col]
//   C: c0=(g,2tg) c1=(g,2tg+1) c2=(g+8,2tg) c3=(g+8,2tg+1)   [row, col]

// ===========================================================================
// NT GEMM on tensor pipe (round-10 proven version, 107us on qkv):
// C[M][Nc] = A[M][K] * W[Nc][K]^T (+ bias)
// 256 thr, BM=128, BN=64, BK=16. Warp grid 4(m) x 2(n), warp tile 32x32.
// ===========================================================================
#define PITCH 20

__global__ __launch_bounds__(256) void gemm_mma_nt(
    const float* __restrict__ A, const float* __restrict__ W,
    const float* __restrict__ bias, float* __restrict__ C,
    int M, int Nc, int K)
{
    __shared__ uint32_t As[128][PITCH];
    __shared__ uint32_t Bs[64][PITCH];
    const int tid = threadIdx.x;
    const int wid = tid >> 5, lane = tid & 31;
    const int g = lane >> 2, tg = lane & 3;
    const int wm = wid & 3, wn = wid >> 2;
    const int m0 = blockIdx.y * 128, n0 = blockIdx.x * 64;
    const int lr = tid >> 2, lc = tid & 3;

    float acc[2][4][4] = {};

    for (int kt = 0; kt < K; kt += 16) {
        float4 av0 = *reinterpret_cast<const float4*>(&A[(size_t)(m0 + lr) * K + kt + lc * 4]);
        float4 av1 = *reinterpret_cast<const float4*>(&A[(size_t)(m0 + lr + 64) * K + kt + lc * 4]);
        float4 wv  = *reinterpret_cast<const float4*>(&W[(size_t)(n0 + lr) * K + kt + lc * 4]);
        __syncthreads();
        As[lr][lc * 4 + 0] = f2t(av0.x); As[lr][lc * 4 + 1] = f2t(av0.y);
        As[lr][lc * 4 + 2] = f2t(av0.z); As[lr][lc * 4 + 3] = f2t(av0.w);
        As[lr + 64][lc * 4 + 0] = f2t(av1.x); As[lr + 64][lc * 4 + 1] = f2t(av1.y);
        As[lr + 64][lc * 4 + 2] = f2t(av1.z); As[lr + 64][lc * 4 + 3] = f2t(av1.w);
        Bs[lr][lc * 4 + 0] = f2t(wv.x); Bs[lr][lc * 4 + 1] = f2t(wv.y);
        Bs[lr][lc * 4 + 2] = f2t(wv.z); Bs[lr][lc * 4 + 3] = f2t(wv.w);
        __syncthreads();

        #pragma unroll
        for (int ks = 0; ks < 2; ++ks) {
            const int k0 = ks * 8;
            uint32_t af[2][4], bfr[4][2];
            #pragma unroll
            for (int mt = 0; mt < 2; ++mt) {
                const int rb = wm * 32 + mt * 16;
                af[mt][0] = As[rb + g][k0 + tg];
                af[mt][1] = As[rb + g + 8][k0 + tg];
                af[mt][2] = As[rb + g][k0 + tg + 4];
                af[mt][3] = As[rb + g + 8][k0 + tg + 4];
            }
            #pragma unroll
            for (int nt = 0; nt < 4; ++nt) {
                const int nb = wn * 32 + nt * 8;
                bfr[nt][0] = Bs[nb + g][k0 + tg];
                bfr[nt][1] = Bs[nb + g][k0 + tg + 4];
            }
            #pragma unroll
            for (int mt = 0; mt < 2; ++mt)
                #pragma unroll
                for (int nt = 0; nt < 4; ++nt)
                    mma8(acc[mt][nt], af[mt], bfr[nt]);
        }
    }

    #pragma unroll
    for (int mt = 0; mt < 2; ++mt) {
        const int row = m0 + wm * 32 + mt * 16 + g;
        #pragma unroll
        for (int nt = 0; nt < 4; ++nt) {
            const int col = n0 + wn * 32 + nt * 8 + tg * 2;
            float2 v0 = {acc[mt][nt][0], acc[mt][nt][1]};
            float2 v1 = {acc[mt][nt][2], acc[mt][nt][3]};
            if (bias) {
                float b0 = bias[col], b1 = bias[col + 1];
                v0.x += b0; v0.y += b1; v1.x += b0; v1.y += b1;
            }
            *reinterpret_cast<float2*>(&C[(size_t)row * Nc + col]) = v0;
            *reinterpret_cast<float2*>(&C[(size_t)(row + 8) * Nc + col]) = v1;
        }
    }
}

// ---------------------------------------------------------------------------
// Normalize q and k head-rows (D=64) in place. One warp per (row, s, h).
// ---------------------------------------------------------------------------
__global__ __launch_bounds__(256) void norm_qk(float* __restrict__ qkv)
{
    int warp = (blockIdx.x * blockDim.x + threadIdx.x) >> 5;
    int lane = threadIdx.x & 31;
    int m = warp >> 5;
    int rem = warp & 31;
    int s = rem >> 4;
    int h = rem & 15;
    float* row = qkv + (size_t)m * THREEC + s * Cc + h * Dd;
    float v0 = row[lane], v1 = row[lane + 32];
    float ss = v0 * v0 + v1 * v1;
    #pragma unroll
    for (int o = 16; o; o >>= 1) ss += __shfl_xor_sync(0xffffffffu, ss, o);
    float inv = rsqrtf(ss);
    row[lane] = v0 * inv;
    row[lane + 32] = v1 * inv;
}

// ===========================================================================
// Fused flash attention, q-tile 128, 8 warps (256 thr).
// Per (bh, q-tile 128) block; k-chunks of 64 stream through smem.
// Warp w owns q-rows [w*16, w*16+16). Per-warp work same as before;
// 2x warps/SMSP for latency cover, half the K/V global traffic.
// Dynamic smem layout (bytes):
//   KP [128][68] u32 @ 0      (rows 0-63: K tf32 chunk; all 128 rows: P)
//   Vs [64][72]  u32 @ 34816
//   Ms [64]      f32 @ 53248
// total 53504
// ===========================================================================
#define AT_KP    0
#define AT_VS    34816
#define AT_MS    53248
#define AT_TOTAL 53504

__global__ __launch_bounds__(256) void attn_fused(
    const float* __restrict__ alibi,
    const int* __restrict__ mask,
    const float* __restrict__ logit_scale)
{
    extern __shared__ char sm[];
    uint32_t (*KP)[68] = reinterpret_cast<uint32_t(*)[68]>(sm + AT_KP);
    uint32_t (*Vs)[72] = reinterpret_cast<uint32_t(*)[72]>(sm + AT_VS);
    float    *Ms       = reinterpret_cast<float*>(sm + AT_MS);

    const int tid = threadIdx.x;
    const int wid = tid >> 5, lane = tid & 31;
    const int g = lane >> 2, tg = lane & 3;
    const int wq = wid * 16;                 // warp's q-row base within 128-tile
    const int bh = blockIdx.y, b = bh >> 4, h = bh & 15;
    const int q0 = blockIdx.x * 128;
    const float sc = __expf(fminf(logit_scale[h], LOGMAX));

    const int cr = tid >> 4;       // loader row (0..15), rows cr + 16i
    const int cc4 = tid & 15;      // loader float4 column

    // ---- stage Q tile (128x64) into KP, pull A-frags into registers ----
    #pragma unroll
    for (int i = 0; i < 8; ++i) {
        int r = cr + i * 16;
        float4 qv = *reinterpret_cast<const float4*>(
            &g_qkv[(size_t)(b * Nn + q0 + r) * THREEC + h * Dd + cc4 * 4]);
        uint4 t = {f2t(qv.x), f2t(qv.y), f2t(qv.z), f2t(qv.w)};
        *reinterpret_cast<uint4*>(&KP[r][cc4 * 4]) = t;
    }
    __syncthreads();
    uint32_t qf[8][4];
    #pragma unroll
    for (int ks = 0; ks < 8; ++ks) {
        qf[ks][0] = KP[wq + g][ks * 8 + tg];
        qf[ks][1] = KP[wq + g + 8][ks * 8 + tg];
        qf[ks][2] = KP[wq + g][ks * 8 + tg + 4];
        qf[ks][3] = KP[wq + g + 8][ks * 8 + tg + 4];
    }

    float m0r = MASKNEG, m1r = MASKNEG, l0 = 0.f, l1 = 0.f;
    float acc_o[8][4] = {};

    const float* al0 = &alibi[((size_t)bh * Nn + q0 + wq + g) * Nn];
    const float* al1 = al0 + (size_t)8 * Nn;

    for (int kt = 0; kt < Nn; kt += 64) {
        __syncthreads();   // prior PV fully consumed KP/Vs
        // ---- load K & V chunk (64 rows x 64): 1024 f4-slots over 256 thr ----
        #pragma unroll
        for (int i = 0; i < 4; ++i) {
            int r = cr + i * 16;
            const float* base = &g_qkv[(size_t)(b * Nn + kt + r) * THREEC + h * Dd + cc4 * 4];
            float4 kv = *reinterpret_cast<const float4*>(base + Cc);
            float4 vv = *reinterpret_cast<const float4*>(base + 2 * Cc);
            uint4 tk = {f2t(kv.x), f2t(kv.y), f2t(kv.z), f2t(kv.w)};
            uint4 tv = {f2t(vv.x), f2t(vv.y), f2t(vv.z), f2t(vv.w)};
            *reinterpret_cast<uint4*>(&KP[r][cc4 * 4]) = tk;
            *reinterpret_cast<uint4*>(&Vs[r][cc4 * 4]) = tv;
        }
        if (tid < 64) Ms[tid] = mask[b * Nn + kt + tid] ? MASKNEG : 0.f;
        __syncthreads();

        // ---- S = Q K^T (16 q x 64 k per warp) ----
        float s[8][4] = {};
        #pragma unroll
        for (int nt = 0; nt < 8; ++nt) {
            #pragma unroll
            for (int ks = 0; ks < 8; ++ks) {
                uint32_t bfr[2];
                bfr[0] = KP[nt * 8 + g][ks * 8 + tg];
                bfr[1] = KP[nt * 8 + g][ks * 8 + tg + 4];
                mma8(s[nt], qf[ks], bfr);
            }
        }

        // ---- scale + alibi + mask; chunk row max ----
        float cm0 = MASKNEG, cm1 = MASKNEG;
        #pragma unroll
        for (int j = 0; j < 8; ++j) {
            const int col = j * 8 + tg * 2;
            float2 a0 = *reinterpret_cast<const float2*>(&al0[kt + col]);
            float2 a1 = *reinterpret_cast<const float2*>(&al1[kt + col]);
            float msk0 = Ms[col], msk1 = Ms[col + 1];
            s[j][0] = fmaf(s[j][0], sc, a0.x + msk0);
            s[j][1] = fmaf(s[j][1], sc, a0.y + msk1);
            s[j][2] = fmaf(s[j][2], sc, a1.x + msk0);
            s[j][3] = fmaf(s[j][3], sc, a1.y + msk1);
            cm0 = fmaxf(cm0, fmaxf(s[j][0], s[j][1]));
            cm1 = fmaxf(cm1, fmaxf(s[j][2], s[j][3]));
        }
        cm0 = fmaxf(cm0, __shfl_xor_sync(0xffffffffu, cm0, 1));
        cm0 = fmaxf(cm0, __shfl_xor_sync(0xffffffffu, cm0, 2));
        cm1 = fmaxf(cm1, __shfl_xor_sync(0xffffffffu, cm1, 1));
        cm1 = fmaxf(cm1, __shfl_xor_sync(0xffffffffu, cm1, 2));

        const float nm0 = fmaxf(m0r, cm0), nm1 = fmaxf(m1r, cm1);
        const float f0 = __expf(m0r - nm0), f1 = __expf(m1r - nm1);
        m0r = nm0; m1r = nm1;

        float rs0 = 0.f, rs1 = 0.f;
        #pragma unroll
        for (int j = 0; j < 8; ++j) {
            s[j][0] = __expf(s[j][0] - nm0); rs0 += s[j][0];
            s[j][1] = __expf(s[j][1] - nm0); rs0 += s[j][1];
            s[j][2] = __expf(s[j][2] - nm1); rs1 += s[j][2];
            s[j][3] = __expf(s[j][3] - nm1); rs1 += s[j][3];
        }
        rs0 += __shfl_xor_sync(0xffffffffu, rs0, 1);
        rs0 += __shfl_xor_sync(0xffffffffu, rs0, 2);
        rs1 += __shfl_xor_sync(0xffffffffu, rs1, 1);
        rs1 += __shfl_xor_sync(0xffffffffu, rs1, 2);
        l0 = l0 * f0 + rs0;
        l1 = l1 * f1 + rs1;

        #pragma unroll
        for (int j = 0; j < 8; ++j) {
            acc_o[j][0] *= f0; acc_o[j][1] *= f0;
            acc_o[j][2] *= f1; acc_o[j][3] *= f1;
        }

        __syncthreads();   // all warps done reading K from KP rows 0-63
        // ---- write P into KP (own 16 rows; wid>=4 rows untouched by K) ----
        #pragma unroll
        for (int j = 0; j < 8; ++j) {
            KP[wq + g][j * 8 + tg * 2]         = f2t(s[j][0]);
            KP[wq + g][j * 8 + tg * 2 + 1]     = f2t(s[j][1]);
            KP[wq + g + 8][j * 8 + tg * 2]     = f2t(s[j][2]);
            KP[wq + g + 8][j * 8 + tg * 2 + 1] = f2t(s[j][3]);
        }
        __syncwarp();

        // ---- O += P V ----
        #pragma unroll
        for (int ks = 0; ks < 8; ++ks) {
            uint32_t pf[4];
            pf[0] = KP[wq + g][ks * 8 + tg];
            pf[1] = KP[wq + g + 8][ks * 8 + tg];
            pf[2] = KP[wq + g][ks * 8 + tg + 4];
            pf[3] = KP[wq + g + 8][ks * 8 + tg + 4];
            #pragma unroll
            for (int nt = 0; nt < 8; ++nt) {
                uint32_t bfr[2];
                bfr[0] = Vs[ks * 8 + tg][nt * 8 + g];
                bfr[1] = Vs[ks * 8 + tg + 4][nt * 8 + g];
                mma8(acc_o[nt], pf, bfr);
            }
        }
    }

    // ---- normalize and write O in [B,N,H*D] layout ----
    const float il0 = 1.0f / l0, il1 = 1.0f / l1;
    const size_t row0 = (size_t)(b * Nn + q0 + wq + g) * Cc + h * Dd;
    const size_t row1 = row0 + (size_t)8 * Cc;
    #pragma unroll
    for (int j = 0; j < 8; ++j) {
        const int col = j * 8 + tg * 2;
        float2 v0 = {acc_o[j][0] * il0, acc_o[j][1] * il0};
        float2 v1 = {acc_o[j][2] * il1, acc_o[j][3] * il1};
        *reinterpret_cast<float2*>(&g_att[row0 + col]) = v0;
        *reinterpret_cast<float2*>(&g_att[row1 + col]) = v1;
    }
}

// ---------------------------------------------------------------------------
// Launch
// ---------------------------------------------------------------------------
extern "C" void kernel_launch(void* const* d_in, const int* in_sizes, int n_in,
                              void* d_out, int out_size)
{
    const float* x           = (const float*)d_in[0];
    const int*   pad_mask    = (const int*)d_in[1];
    const float* alibi       = (const float*)d_in[2];
    const float* qkv_w       = (const float*)d_in[3];
    const float* proj_w      = (const float*)d_in[4];
    const float* proj_b      = (const float*)d_in[5];
    const float* logit_scale = (const float*)d_in[6];
    float*       out         = (float*)d_out;

    void *qkvp = nullptr, *attp = nullptr;
    cudaGetSymbolAddress(&qkvp, g_qkv);
    cudaGetSymbolAddress(&attp, g_att);

    static int attr_set = 0;
    if (!attr_set) {
        cudaFuncSetAttribute(attn_fused, cudaFuncAttributeMaxDynamicSharedMemorySize, AT_TOTAL);
        attr_set = 1;
    }

    // 1. qkv projection (tf32 mma)
    gemm_mma_nt<<<dim3(THREEC / 64, MROWS / 128), 256>>>(
        x, qkv_w, nullptr, (float*)qkvp, MROWS, THREEC, Cc);

    // 2. normalize q and k head-rows in place
    norm_qk<<<(MROWS * 2 * Hh) / 8, 256>>>((float*)qkvp);

    // 3-5. fused scores + softmax + PV (q-tile 128, 8 warps)
    attn_fused<<<dim3(Nn / 128, Bb * Hh), 256, AT_TOTAL>>>(alibi, pad_mask, logit_scale);

    // 6. output projection + bias (tf32 mma)
    gemm_mma_nt<<<dim3(Cc / 64, MROWS / 128), 256>>>(
        (const float*)attp, proj_w, proj_b, out, MROWS, Cc, Cc);
}

// round 15
// speedup vs baseline: 1.0038x; 1.0038x over previous
#include <cuda_runtime.h>
#include <math.h>
#include <stdint.h>

// Problem constants
#define Bb      2
#define Nn      2048
#define Cc      1024
#define Hh      16
#define Dd      64
#define MROWS   (Bb * Nn)      // 4096
#define THREEC  (3 * Cc)       // 3072
#define LOGMAX  4.6051701859880914f  // ln(100)
#define MASKNEG (-1e30f)

// ---------------------------------------------------------------------------
// Scratch
// ---------------------------------------------------------------------------
__device__ float g_qkv[(size_t)MROWS * THREEC];          // 50 MB
__device__ float g_att[(size_t)MROWS * Cc];              // 16 MB

// ---------------------------------------------------------------------------
// tf32 mma.sync helpers (sm_80+ PTX — safe under compute_103 family target)
// ---------------------------------------------------------------------------
__device__ __forceinline__ uint32_t f2t(float x) {
    uint32_t u;
    asm("cvt.rna.tf32.f32 %0, %1;" : "=r"(u) : "f"(x));
    return u;
}

__device__ __forceinline__ void mma8(float* d, const uint32_t* a, const uint32_t* b) {
    asm volatile(
        "mma.sync.aligned.m16n8k8.row.col.f32.tf32.tf32.f32 "
        "{%0,%1,%2,%3}, {%4,%5,%6,%7}, {%8,%9}, {%0,%1,%2,%3};"
        : "+f"(d[0]), "+f"(d[1]), "+f"(d[2]), "+f"(d[3])
        : "r"(a[0]), "r"(a[1]), "r"(a[2]), "r"(a[3]), "r"(b[0]), "r"(b[1]));
}
// Frag maps (g = lane>>2, tg = lane&3):
//   A: a0=(g,tg) a1=(g+8,tg) a2=(g,tg+4) a3=(g+8,tg+4)      [row, k]
//   B: b0=(k=tg,n=g) b1=(k=tg+4,n=g)                         [k, col]
//   C: c0=(g,2tg) c1=(g,2tg+1) c2=(g+8,2tg) c3=(g+8,2tg+1)   [row, col]

// ===========================================================================
// NT GEMM on tensor pipe (round-10 proven version, 107us on qkv):
// C[M][Nc] = A[M][K] * W[Nc][K]^T (+ bias)
// ===========================================================================
#define PITCH 20

__global__ __launch_bounds__(256) void gemm_mma_nt(
    const float* __restrict__ A, const float* __restrict__ W,
    const float* __restrict__ bias, float* __restrict__ C,
    int M, int Nc, int K)
{
    __shared__ uint32_t As[128][PITCH];
    __shared__ uint32_t Bs[64][PITCH];
    const int tid = threadIdx.x;
    const int wid = tid >> 5, lane = tid & 31;
    const int g = lane >> 2, tg = lane & 3;
    const int wm = wid & 3, wn = wid >> 2;
    const int m0 = blockIdx.y * 128, n0 = blockIdx.x * 64;
    const int lr = tid >> 2, lc = tid & 3;

    float acc[2][4][4] = {};

    for (int kt = 0; kt < K; kt += 16) {
        float4 av0 = *reinterpret_cast<const float4*>(&A[(size_t)(m0 + lr) * K + kt + lc * 4]);
        float4 av1 = *reinterpret_cast<const float4*>(&A[(size_t)(m0 + lr + 64) * K + kt + lc * 4]);
        float4 wv  = *reinterpret_cast<const float4*>(&W[(size_t)(n0 + lr) * K + kt + lc * 4]);
        __syncthreads();
        As[lr][lc * 4 + 0] = f2t(av0.x); As[lr][lc * 4 + 1] = f2t(av0.y);
        As[lr][lc * 4 + 2] = f2t(av0.z); As[lr][lc * 4 + 3] = f2t(av0.w);
        As[lr + 64][lc * 4 + 0] = f2t(av1.x); As[lr + 64][lc * 4 + 1] = f2t(av1.y);
        As[lr + 64][lc * 4 + 2] = f2t(av1.z); As[lr + 64][lc * 4 + 3] = f2t(av1.w);
        Bs[lr][lc * 4 + 0] = f2t(wv.x); Bs[lr][lc * 4 + 1] = f2t(wv.y);
        Bs[lr][lc * 4 + 2] = f2t(wv.z); Bs[lr][lc * 4 + 3] = f2t(wv.w);
        __syncthreads();

        #pragma unroll
        for (int ks = 0; ks < 2; ++ks) {
            const int k0 = ks * 8;
            uint32_t af[2][4], bfr[4][2];
            #pragma unroll
            for (int mt = 0; mt < 2; ++mt) {
                const int rb = wm * 32 + mt * 16;
                af[mt][0] = As[rb + g][k0 + tg];
                af[mt][1] = As[rb + g + 8][k0 + tg];
                af[mt][2] = As[rb + g][k0 + tg + 4];
                af[mt][3] = As[rb + g + 8][k0 + tg + 4];
            }
            #pragma unroll
            for (int nt = 0; nt < 4; ++nt) {
                const int nb = wn * 32 + nt * 8;
                bfr[nt][0] = Bs[nb + g][k0 + tg];
                bfr[nt][1] = Bs[nb + g][k0 + tg + 4];
            }
            #pragma unroll
            for (int mt = 0; mt < 2; ++mt)
                #pragma unroll
                for (int nt = 0; nt < 4; ++nt)
                    mma8(acc[mt][nt], af[mt], bfr[nt]);
        }
    }

    #pragma unroll
    for (int mt = 0; mt < 2; ++mt) {
        const int row = m0 + wm * 32 + mt * 16 + g;
        #pragma unroll
        for (int nt = 0; nt < 4; ++nt) {
            const int col = n0 + wn * 32 + nt * 8 + tg * 2;
            float2 v0 = {acc[mt][nt][0], acc[mt][nt][1]};
            float2 v1 = {acc[mt][nt][2], acc[mt][nt][3]};
            if (bias) {
                float b0 = bias[col], b1 = bias[col + 1];
                v0.x += b0; v0.y += b1; v1.x += b0; v1.y += b1;
            }
            *reinterpret_cast<float2*>(&C[(size_t)row * Nc + col]) = v0;
            *reinterpret_cast<float2*>(&C[(size_t)(row + 8) * Nc + col]) = v1;
        }
    }
}

// ---------------------------------------------------------------------------
// Normalize q and k head-rows (D=64) in place. One warp per (row, s, h).
// ---------------------------------------------------------------------------
__global__ __launch_bounds__(256) void norm_qk(float* __restrict__ qkv)
{
    int warp = (blockIdx.x * blockDim.x + threadIdx.x) >> 5;
    int lane = threadIdx.x & 31;
    int m = warp >> 5;
    int rem = warp & 31;
    int s = rem >> 4;
    int h = rem & 15;
    float* row = qkv + (size_t)m * THREEC + s * Cc + h * Dd;
    float v0 = row[lane], v1 = row[lane + 32];
    float ss = v0 * v0 + v1 * v1;
    #pragma unroll
    for (int o = 16; o; o >>= 1) ss += __shfl_xor_sync(0xffffffffu, ss, o);
    float inv = rsqrtf(ss);
    row[lane] = v0 * inv;
    row[lane + 32] = v1 * inv;
}

// ===========================================================================
// Fused flash attention (round-11 skeleton: 128 thr, q-tile 64) with
// PAIRED-K interleaved smem layouts for K and V so each mma B-frag is one
// LDS.64 instead of two LDS.32.
//
// Layout: X[ks][tg][n][j] at u32 offset ks*548 + tg*136 + n*2 + j,
//   holding element (k = ks*8 + j*4 + tg, n).  Region = 8*548 = 4384 u32.
//   tg-stride 136 = 8 mod 32  -> LDS.64 conflict-free (both phases)
//   ks-stride 548 = 4 mod 32  -> K-convert 4xSTS.32 scatter conflict-free
// Q stages flat [64][68] in VI before the loop; P overwrites KI flat.
// ===========================================================================
#define KSTR 548
#define TSTR 136
#define IREG 4384

__global__ __launch_bounds__(128) void attn_fused(
    const float* __restrict__ alibi,
    const int* __restrict__ mask,
    const float* __restrict__ logit_scale)
{
    __shared__ __align__(16) uint32_t KI[IREG];   // K interleaved, then P flat
    __shared__ __align__(16) uint32_t VI[IREG];   // Q flat staging, then V interleaved
    __shared__ float Ms[64];

    const int tid = threadIdx.x;
    const int wid = tid >> 5, lane = tid & 31;
    const int g = lane >> 2, tg = lane & 3;
    const int wq = wid * 16;
    const int bh = blockIdx.y, b = bh >> 4, h = bh & 15;
    const int q0 = blockIdx.x * 64;
    const float sc = __expf(fminf(logit_scale[h], LOGMAX));

    const int cr = tid >> 4;       // loader row base (rows cr + 8i)
    const int cc4 = tid & 15;      // loader float4 column

    // ---- stage Q tile flat into VI, extract A-frags ----
    #pragma unroll
    for (int i = 0; i < 8; ++i) {
        int r = cr + i * 8;
        float4 qv = *reinterpret_cast<const float4*>(
            &g_qkv[(size_t)(b * Nn + q0 + r) * THREEC + h * Dd + cc4 * 4]);
        uint4 t = {f2t(qv.x), f2t(qv.y), f2t(qv.z), f2t(qv.w)};
        *reinterpret_cast<uint4*>(&VI[r * 68 + cc4 * 4]) = t;
    }
    __syncthreads();
    uint32_t qf[8][4];
    #pragma unroll
    for (int ks = 0; ks < 8; ++ks) {
        qf[ks][0] = VI[(wq + g) * 68 + ks * 8 + tg];
        qf[ks][1] = VI[(wq + g + 8) * 68 + ks * 8 + tg];
        qf[ks][2] = VI[(wq + g) * 68 + ks * 8 + tg + 4];
        qf[ks][3] = VI[(wq + g + 8) * 68 + ks * 8 + tg + 4];
    }

    float m0r = MASKNEG, m1r = MASKNEG, l0 = 0.f, l1 = 0.f;
    float acc_o[8][4] = {};

    const float* al0 = &alibi[((size_t)bh * Nn + q0 + wq + g) * Nn];
    const float* al1 = al0 + (size_t)8 * Nn;

    for (int kt = 0; kt < Nn; kt += 64) {
        __syncthreads();   // prior PV consumed KI(P) and VI(V); Q frags extracted
        // ---- load K & V chunk into interleaved layouts ----
        #pragma unroll
        for (int i = 0; i < 8; ++i) {
            int r = cr + i * 8;
            const float* base = &g_qkv[(size_t)(b * Nn + kt + r) * THREEC + h * Dd + cc4 * 4];
            float4 kv = *reinterpret_cast<const float4*>(base + Cc);
            float4 vv = *reinterpret_cast<const float4*>(base + 2 * Cc);
            // K element (k = cc4*4+m, n = r):  ks=cc4>>1, tg=m, j=cc4&1
            uint32_t kbase = (uint32_t)(cc4 >> 1) * KSTR + (cc4 & 1) + r * 2;
            KI[kbase + 0 * TSTR] = f2t(kv.x);
            KI[kbase + 1 * TSTR] = f2t(kv.y);
            KI[kbase + 2 * TSTR] = f2t(kv.z);
            KI[kbase + 3 * TSTR] = f2t(kv.w);
            // V element (k = r, n = cc4*4+m):  ks=r>>3, tg=r&3, j=(r>>2)&1
            uint32_t vbase = (uint32_t)(r >> 3) * KSTR + (r & 3) * TSTR
                           + ((r >> 2) & 1) + cc4 * 8;
            VI[vbase + 0] = f2t(vv.x);
            VI[vbase + 2] = f2t(vv.y);
            VI[vbase + 4] = f2t(vv.z);
            VI[vbase + 6] = f2t(vv.w);
        }
        if (tid < 64) Ms[tid] = mask[b * Nn + kt + tid] ? MASKNEG : 0.f;
        __syncthreads();

        // ---- S = Q K^T  (B-frag = one LDS.64 from KI) ----
        float s[8][4] = {};
        #pragma unroll
        for (int nt = 0; nt < 8; ++nt) {
            const uint32_t nrow2 = (uint32_t)(nt * 8 + g) * 2;
            #pragma unroll
            for (int ks = 0; ks < 8; ++ks) {
                uint2 bb = *reinterpret_cast<const uint2*>(
                    &KI[(uint32_t)ks * KSTR + (uint32_t)tg * TSTR + nrow2]);
                mma8(s[nt], qf[ks], reinterpret_cast<const uint32_t*>(&bb));
            }
        }

        // ---- scale + alibi + mask; chunk row max ----
        float cm0 = MASKNEG, cm1 = MASKNEG;
        #pragma unroll
        for (int j = 0; j < 8; ++j) {
            const int col = j * 8 + tg * 2;
            float2 a0 = *reinterpret_cast<const float2*>(&al0[kt + col]);
            float2 a1 = *reinterpret_cast<const float2*>(&al1[kt + col]);
            float msk0 = Ms[col], msk1 = Ms[col + 1];
            s[j][0] = fmaf(s[j][0], sc, a0.x + msk0);
            s[j][1] = fmaf(s[j][1], sc, a0.y + msk1);
            s[j][2] = fmaf(s[j][2], sc, a1.x + msk0);
            s[j][3] = fmaf(s[j][3], sc, a1.y + msk1);
            cm0 = fmaxf(cm0, fmaxf(s[j][0], s[j][1]));
            cm1 = fmaxf(cm1, fmaxf(s[j][2], s[j][3]));
        }
        cm0 = fmaxf(cm0, __shfl_xor_sync(0xffffffffu, cm0, 1));
        cm0 = fmaxf(cm0, __shfl_xor_sync(0xffffffffu, cm0, 2));
        cm1 = fmaxf(cm1, __shfl_xor_sync(0xffffffffu, cm1, 1));
        cm1 = fmaxf(cm1, __shfl_xor_sync(0xffffffffu, cm1, 2));

        const float nm0 = fmaxf(m0r, cm0), nm1 = fmaxf(m1r, cm1);
        const float f0 = __expf(m0r - nm0), f1 = __expf(m1r - nm1);
        m0r = nm0; m1r = nm1;

        float rs0 = 0.f, rs1 = 0.f;
        #pragma unroll
        for (int j = 0; j < 8; ++j) {
            s[j][0] = __expf(s[j][0] - nm0); rs0 += s[j][0];
            s[j][1] = __expf(s[j][1] - nm0); rs0 += s[j][1];
            s[j][2] = __expf(s[j][2] - nm1); rs1 += s[j][2];
            s[j][3] = __expf(s[j][3] - nm1); rs1 += s[j][3];
        }
        rs0 += __shfl_xor_sync(0xffffffffu, rs0, 1);
        rs0 += __shfl_xor_sync(0xffffffffu, rs0, 2);
        rs1 += __shfl_xor_sync(0xffffffffu, rs1, 1);
        rs1 += __shfl_xor_sync(0xffffffffu, rs1, 2);
        l0 = l0 * f0 + rs0;
        l1 = l1 * f1 + rs1;

        #pragma unroll
        for (int j = 0; j < 8; ++j) {
            acc_o[j][0] *= f0; acc_o[j][1] *= f0;
            acc_o[j][2] *= f1; acc_o[j][3] *= f1;
        }

        __syncthreads();   // all warps done reading K from KI
        // ---- write P flat into KI (own 16 rows) ----
        #pragma unroll
        for (int j = 0; j < 8; ++j) {
            KI[(wq + g) * 68 + j * 8 + tg * 2]         = f2t(s[j][0]);
            KI[(wq + g) * 68 + j * 8 + tg * 2 + 1]     = f2t(s[j][1]);
            KI[(wq + g + 8) * 68 + j * 8 + tg * 2]     = f2t(s[j][2]);
            KI[(wq + g + 8) * 68 + j * 8 + tg * 2 + 1] = f2t(s[j][3]);
        }
        __syncwarp();

        // ---- O += P V  (V B-frag = one LDS.64 from VI) ----
        #pragma unroll
        for (int ks = 0; ks < 8; ++ks) {
            uint32_t pf[4];
            pf[0] = KI[(wq + g) * 68 + ks * 8 + tg];
            pf[1] = KI[(wq + g + 8) * 68 + ks * 8 + tg];
            pf[2] = KI[(wq + g) * 68 + ks * 8 + tg + 4];
            pf[3] = KI[(wq + g + 8) * 68 + ks * 8 + tg + 4];
            #pragma unroll
            for (int nt = 0; nt < 8; ++nt) {
                uint2 bb = *reinterpret_cast<const uint2*>(
                    &VI[(uint32_t)ks * KSTR + (uint32_t)tg * TSTR + (uint32_t)(nt * 8 + g) * 2]);
                mma8(acc_o[nt], pf, reinterpret_cast<const uint32_t*>(&bb));
            }
        }
    }

    // ---- normalize and write O in [B,N,H*D] layout ----
    const float il0 = 1.0f / l0, il1 = 1.0f / l1;
    const size_t row0 = (size_t)(b * Nn + q0 + wq + g) * Cc + h * Dd;
    const size_t row1 = row0 + (size_t)8 * Cc;
    #pragma unroll
    for (int j = 0; j < 8; ++j) {
        const int col = j * 8 + tg * 2;
        float2 v0 = {acc_o[j][0] * il0, acc_o[j][1] * il0};
        float2 v1 = {acc_o[j][2] * il1, acc_o[j][3] * il1};
        *reinterpret_cast<float2*>(&g_att[row0 + col]) = v0;
        *reinterpret_cast<float2*>(&g_att[row1 + col]) = v1;
    }
}

// ---------------------------------------------------------------------------
// Launch
// ---------------------------------------------------------------------------
extern "C" void kernel_launch(void* const* d_in, const int* in_sizes, int n_in,
                              void* d_out, int out_size)
{
    const float* x           = (const float*)d_in[0];
    const int*   pad_mask    = (const int*)d_in[1];
    const float* alibi       = (const float*)d_in[2];
    const float* qkv_w       = (const float*)d_in[3];
    const float* proj_w      = (const float*)d_in[4];
    const float* proj_b      = (const float*)d_in[5];
    const float* logit_scale = (const float*)d_in[6];
    float*       out         = (float*)d_out;

    void *qkvp = nullptr, *attp = nullptr;
    cudaGetSymbolAddress(&qkvp, g_qkv);
    cudaGetSymbolAddress(&attp, g_att);

    // 1. qkv projection (tf32 mma)
    gemm_mma_nt<<<dim3(THREEC / 64, MROWS / 128), 256>>>(
        x, qkv_w, nullptr, (float*)qkvp, MROWS, THREEC, Cc);

    // 2. normalize q and k head-rows in place
    norm_qk<<<(MROWS * 2 * Hh) / 8, 256>>>((float*)qkvp);

    // 3-5. fused scores + softmax + PV (paired-K LDS.64 layouts)
    attn_fused<<<dim3(Nn / 64, Bb * Hh), 128>>>(alibi, pad_mask, logit_scale);

    // 6. output projection + bias (tf32 mma)
    gemm_mma_nt<<<dim3(Cc / 64, MROWS / 128), 256>>>(
        (const float*)attp, proj_w, proj_b, out, MROWS, Cc, Cc);
}

// round 16
// speedup vs baseline: 1.2667x; 1.2620x over previous
#include <cuda_runtime.h>
#include <math.h>
#include <stdint.h>

// Problem constants
#define Bb      2
#define Nn      2048
#define Cc      1024
#define Hh      16
#define Dd      64
#define MROWS   (Bb * Nn)      // 4096
#define THREEC  (3 * Cc)       // 3072
#define LOGMAX  4.6051701859880914f  // ln(100)
#define MASKNEG (-1e30f)

// ---------------------------------------------------------------------------
// Scratch
// ---------------------------------------------------------------------------
__device__ float g_qkv[(size_t)MROWS * THREEC];          // 50 MB
__device__ float g_att[(size_t)MROWS * Cc];              // 16 MB

// ---------------------------------------------------------------------------
// tf32 mma.sync helpers (sm_80+ PTX — safe under compute_103 family target)
// ---------------------------------------------------------------------------
__device__ __forceinline__ uint32_t f2t(float x) {
    uint32_t u;
    asm("cvt.rna.tf32.f32 %0, %1;" : "=r"(u) : "f"(x));
    return u;
}

__device__ __forceinline__ void mma8(float* d, const uint32_t* a, const uint32_t* b) {
    asm volatile(
        "mma.sync.aligned.m16n8k8.row.col.f32.tf32.tf32.f32 "
        "{%0,%1,%2,%3}, {%4,%5,%6,%7}, {%8,%9}, {%0,%1,%2,%3};"
        : "+f"(d[0]), "+f"(d[1]), "+f"(d[2]), "+f"(d[3])
        : "r"(a[0]), "r"(a[1]), "r"(a[2]), "r"(a[3]), "r"(b[0]), "r"(b[1]));
}
// Frag maps (g = lane>>2, tg = lane&3):
//   A: a0=(g,tg) a1=(g+8,tg) a2=(g,tg+4) a3=(g+8,tg+4)      [row, k]
//   B: b0=(k=tg,n=g) b1=(k=tg+4,n=g)                         [k, col]
//   C: c0=(g,2tg) c1=(g,2tg+1) c2=(g+8,2tg) c3=(g+8,2tg+1)   [row, col]

// ===========================================================================
// NT GEMM, wide tiles: C[M][Nc] = A[M][K] * W[Nc][K]^T (+ bias)
// 256 thr, BM=128, BN=128, BK=16. Warp grid 2(m) x 4(n), warp tile 64x32.
// 24 LDS per 32 mma per k-step (vs 16 per 8 before): 2.7x fewer smem
// wavefronts per FLOP — targets the measured L1=68% bottleneck.
// ===========================================================================
#define PITCH 20

__global__ __launch_bounds__(256) void gemm_mma_nt(
    const float* __restrict__ A, const float* __restrict__ W,
    const float* __restrict__ bias, float* __restrict__ C,
    int M, int Nc, int K)
{
    __shared__ uint32_t As[128][PITCH];
    __shared__ uint32_t Bs[128][PITCH];
    const int tid = threadIdx.x;
    const int wid = tid >> 5, lane = tid & 31;
    const int g = lane >> 2, tg = lane & 3;
    const int wm = wid & 1, wn = wid >> 1;          // 2 m-warps x 4 n-warps
    const int m0 = blockIdx.y * 128, n0 = blockIdx.x * 128;
    const int lr = tid >> 2, lc = tid & 3;

    float acc[4][4][4] = {};

    for (int kt = 0; kt < K; kt += 16) {
        float4 av0 = *reinterpret_cast<const float4*>(&A[(size_t)(m0 + lr) * K + kt + lc * 4]);
        float4 av1 = *reinterpret_cast<const float4*>(&A[(size_t)(m0 + lr + 64) * K + kt + lc * 4]);
        float4 wv0 = *reinterpret_cast<const float4*>(&W[(size_t)(n0 + lr) * K + kt + lc * 4]);
        float4 wv1 = *reinterpret_cast<const float4*>(&W[(size_t)(n0 + lr + 64) * K + kt + lc * 4]);
        __syncthreads();
        {
            uint4 t0 = {f2t(av0.x), f2t(av0.y), f2t(av0.z), f2t(av0.w)};
            uint4 t1 = {f2t(av1.x), f2t(av1.y), f2t(av1.z), f2t(av1.w)};
            uint4 t2 = {f2t(wv0.x), f2t(wv0.y), f2t(wv0.z), f2t(wv0.w)};
            uint4 t3 = {f2t(wv1.x), f2t(wv1.y), f2t(wv1.z), f2t(wv1.w)};
            *reinterpret_cast<uint4*>(&As[lr][lc * 4]) = t0;
            *reinterpret_cast<uint4*>(&As[lr + 64][lc * 4]) = t1;
            *reinterpret_cast<uint4*>(&Bs[lr][lc * 4]) = t2;
            *reinterpret_cast<uint4*>(&Bs[lr + 64][lc * 4]) = t3;
        }
        __syncthreads();

        #pragma unroll
        for (int ks = 0; ks < 2; ++ks) {
            const int k0 = ks * 8;
            uint32_t af[4][4], bfr[4][2];
            #pragma unroll
            for (int mt = 0; mt < 4; ++mt) {
                const int rb = wm * 64 + mt * 16;
                af[mt][0] = As[rb + g][k0 + tg];
                af[mt][1] = As[rb + g + 8][k0 + tg];
                af[mt][2] = As[rb + g][k0 + tg + 4];
                af[mt][3] = As[rb + g + 8][k0 + tg + 4];
            }
            #pragma unroll
            for (int nt = 0; nt < 4; ++nt) {
                const int nb = wn * 32 + nt * 8;
                bfr[nt][0] = Bs[nb + g][k0 + tg];
                bfr[nt][1] = Bs[nb + g][k0 + tg + 4];
            }
            #pragma unroll
            for (int mt = 0; mt < 4; ++mt)
                #pragma unroll
                for (int nt = 0; nt < 4; ++nt)
                    mma8(acc[mt][nt], af[mt], bfr[nt]);
        }
    }

    #pragma unroll
    for (int mt = 0; mt < 4; ++mt) {
        const int row = m0 + wm * 64 + mt * 16 + g;
        #pragma unroll
        for (int nt = 0; nt < 4; ++nt) {
            const int col = n0 + wn * 32 + nt * 8 + tg * 2;
            float2 v0 = {acc[mt][nt][0], acc[mt][nt][1]};
            float2 v1 = {acc[mt][nt][2], acc[mt][nt][3]};
            if (bias) {
                float b0 = bias[col], b1 = bias[col + 1];
                v0.x += b0; v0.y += b1; v1.x += b0; v1.y += b1;
            }
            *reinterpret_cast<float2*>(&C[(size_t)row * Nc + col]) = v0;
            *reinterpret_cast<float2*>(&C[(size_t)(row + 8) * Nc + col]) = v1;
        }
    }
}

// ---------------------------------------------------------------------------
// Normalize q and k head-rows (D=64) in place. One warp per (row, s, h).
// ---------------------------------------------------------------------------
__global__ __launch_bounds__(256) void norm_qk(float* __restrict__ qkv)
{
    int warp = (blockIdx.x * blockDim.x + threadIdx.x) >> 5;
    int lane = threadIdx.x & 31;
    int m = warp >> 5;
    int rem = warp & 31;
    int s = rem >> 4;
    int h = rem & 15;
    float* row = qkv + (size_t)m * THREEC + s * Cc + h * Dd;
    float v0 = row[lane], v1 = row[lane + 32];
    float ss = v0 * v0 + v1 * v1;
    #pragma unroll
    for (int o = 16; o; o >>= 1) ss += __shfl_xor_sync(0xffffffffu, ss, o);
    float inv = rsqrtf(ss);
    row[lane] = v0 * inv;
    row[lane + 32] = v1 * inv;
}

// ===========================================================================
// Fused flash attention — round-11 version VERBATIM (best known: ~613us).
// Per (bh, q-tile 64) block, 128 thr, k-chunks of 64 through smem.
// KP holds K then is reused for P; Vs holds V. Scores never touch DRAM.
// ===========================================================================
__global__ __launch_bounds__(128) void attn_fused(
    const float* __restrict__ alibi,
    const int* __restrict__ mask,
    const float* __restrict__ logit_scale)
{
    __shared__ uint32_t KP[64][68];   // K chunk (tf32), then P (tf32)
    __shared__ uint32_t Vs[64][72];   // V chunk (tf32)
    __shared__ float    Ms[64];       // additive mask: 0 or -1e30

    const int tid = threadIdx.x;
    const int wid = tid >> 5, lane = tid & 31;
    const int g = lane >> 2, tg = lane & 3;
    const int wq = wid * 16;
    const int bh = blockIdx.y, b = bh >> 4, h = bh & 15;
    const int q0 = blockIdx.x * 64;
    const float sc = __expf(fminf(logit_scale[h], LOGMAX));

    // ---- stage Q tile (64x64) into KP, pull A-frags into registers ----
    #pragma unroll
    for (int i = 0; i < 8; ++i) {
        int slot = tid + i * 128;
        int r = slot >> 4, c4 = slot & 15;
        float4 qv = *reinterpret_cast<const float4*>(
            &g_qkv[(size_t)(b * Nn + q0 + r) * THREEC + h * Dd + c4 * 4]);
        KP[r][c4 * 4 + 0] = f2t(qv.x); KP[r][c4 * 4 + 1] = f2t(qv.y);
        KP[r][c4 * 4 + 2] = f2t(qv.z); KP[r][c4 * 4 + 3] = f2t(qv.w);
    }
    __syncthreads();
    uint32_t qf[8][4];
    #pragma unroll
    for (int ks = 0; ks < 8; ++ks) {
        qf[ks][0] = KP[wq + g][ks * 8 + tg];
        qf[ks][1] = KP[wq + g + 8][ks * 8 + tg];
        qf[ks][2] = KP[wq + g][ks * 8 + tg + 4];
        qf[ks][3] = KP[wq + g + 8][ks * 8 + tg + 4];
    }

    float m0r = MASKNEG, m1r = MASKNEG, l0 = 0.f, l1 = 0.f;
    float acc_o[8][4] = {};

    const float* al0 = &alibi[((size_t)bh * Nn + q0 + wq + g) * Nn];
    const float* al1 = al0 + (size_t)8 * Nn;

    for (int kt = 0; kt < Nn; kt += 64) {
        __syncthreads();   // prior PV (KP=P, Vs) fully consumed
        // ---- load K & V chunk (64 rows x 64), mask ----
        #pragma unroll
        for (int i = 0; i < 8; ++i) {
            int slot = tid + i * 128;
            int r = slot >> 4, c4 = slot & 15;
            const float* base = &g_qkv[(size_t)(b * Nn + kt + r) * THREEC + h * Dd];
            float4 kv = *reinterpret_cast<const float4*>(base + Cc + c4 * 4);
            float4 vv = *reinterpret_cast<const float4*>(base + 2 * Cc + c4 * 4);
            KP[r][c4 * 4 + 0] = f2t(kv.x); KP[r][c4 * 4 + 1] = f2t(kv.y);
            KP[r][c4 * 4 + 2] = f2t(kv.z); KP[r][c4 * 4 + 3] = f2t(kv.w);
            Vs[r][c4 * 4 + 0] = f2t(vv.x); Vs[r][c4 * 4 + 1] = f2t(vv.y);
            Vs[r][c4 * 4 + 2] = f2t(vv.z); Vs[r][c4 * 4 + 3] = f2t(vv.w);
        }
        if (tid < 64) Ms[tid] = mask[b * Nn + kt + tid] ? MASKNEG : 0.f;
        __syncthreads();

        // ---- S = Q K^T (16 q x 64 k per warp) ----
        float s[8][4] = {};
        #pragma unroll
        for (int nt = 0; nt < 8; ++nt) {
            #pragma unroll
            for (int ks = 0; ks < 8; ++ks) {
                uint32_t bfr[2];
                bfr[0] = KP[nt * 8 + g][ks * 8 + tg];
                bfr[1] = KP[nt * 8 + g][ks * 8 + tg + 4];
                mma8(s[nt], qf[ks], bfr);
            }
        }

        // ---- scale + alibi + mask; chunk row max ----
        float cm0 = MASKNEG, cm1 = MASKNEG;
        #pragma unroll
        for (int j = 0; j < 8; ++j) {
            const int col = j * 8 + tg * 2;
            float2 a0 = *reinterpret_cast<const float2*>(&al0[kt + col]);
            float2 a1 = *reinterpret_cast<const float2*>(&al1[kt + col]);
            float msk0 = Ms[col], msk1 = Ms[col + 1];
            s[j][0] = fmaf(s[j][0], sc, a0.x + msk0);
            s[j][1] = fmaf(s[j][1], sc, a0.y + msk1);
            s[j][2] = fmaf(s[j][2], sc, a1.x + msk0);
            s[j][3] = fmaf(s[j][3], sc, a1.y + msk1);
            cm0 = fmaxf(cm0, fmaxf(s[j][0], s[j][1]));
            cm1 = fmaxf(cm1, fmaxf(s[j][2], s[j][3]));
        }
        cm0 = fmaxf(cm0, __shfl_xor_sync(0xffffffffu, cm0, 1));
        cm0 = fmaxf(cm0, __shfl_xor_sync(0xffffffffu, cm0, 2));
        cm1 = fmaxf(cm1, __shfl_xor_sync(0xffffffffu, cm1, 1));
        cm1 = fmaxf(cm1, __shfl_xor_sync(0xffffffffu, cm1, 2));

        const float nm0 = fmaxf(m0r, cm0), nm1 = fmaxf(m1r, cm1);
        const float f0 = __expf(m0r - nm0), f1 = __expf(m1r - nm1);
        m0r = nm0; m1r = nm1;

        float rs0 = 0.f, rs1 = 0.f;
        #pragma unroll
        for (int j = 0; j < 8; ++j) {
            s[j][0] = __expf(s[j][0] - nm0); rs0 += s[j][0];
            s[j][1] = __expf(s[j][1] - nm0); rs0 += s[j][1];
            s[j][2] = __expf(s[j][2] - nm1); rs1 += s[j][2];
            s[j][3] = __expf(s[j][3] - nm1); rs1 += s[j][3];
        }
        rs0 += __shfl_xor_sync(0xffffffffu, rs0, 1);
        rs0 += __shfl_xor_sync(0xffffffffu, rs0, 2);
        rs1 += __shfl_xor_sync(0xffffffffu, rs1, 1);
        rs1 += __shfl_xor_sync(0xffffffffu, rs1, 2);
        l0 = l0 * f0 + rs0;
        l1 = l1 * f1 + rs1;

        #pragma unroll
        for (int j = 0; j < 8; ++j) {
            acc_o[j][0] *= f0; acc_o[j][1] *= f0;
            acc_o[j][2] *= f1; acc_o[j][3] *= f1;
        }

        __syncthreads();   // all warps done reading K from KP
        // ---- write P into KP (own rows only) ----
        #pragma unroll
        for (int j = 0; j < 8; ++j) {
            KP[wq + g][j * 8 + tg * 2]         = f2t(s[j][0]);
            KP[wq + g][j * 8 + tg * 2 + 1]     = f2t(s[j][1]);
            KP[wq + g + 8][j * 8 + tg * 2]     = f2t(s[j][2]);
            KP[wq + g + 8][j * 8 + tg * 2 + 1] = f2t(s[j][3]);
        }
        __syncwarp();

        // ---- O += P V ----
        #pragma unroll
        for (int ks = 0; ks < 8; ++ks) {
            uint32_t pf[4];
            pf[0] = KP[wq + g][ks * 8 + tg];
            pf[1] = KP[wq + g + 8][ks * 8 + tg];
            pf[2] = KP[wq + g][ks * 8 + tg + 4];
            pf[3] = KP[wq + g + 8][ks * 8 + tg + 4];
            #pragma unroll
            for (int nt = 0; nt < 8; ++nt) {
                uint32_t bfr[2];
                bfr[0] = Vs[ks * 8 + tg][nt * 8 + g];
                bfr[1] = Vs[ks * 8 + tg + 4][nt * 8 + g];
                mma8(acc_o[nt], pf, bfr);
            }
        }
    }

    // ---- normalize and write O in [B,N,H*D] layout ----
    const float il0 = 1.0f / l0, il1 = 1.0f / l1;
    const size_t row0 = (size_t)(b * Nn + q0 + wq + g) * Cc + h * Dd;
    const size_t row1 = row0 + (size_t)8 * Cc;
    #pragma unroll
    for (int j = 0; j < 8; ++j) {
        const int col = j * 8 + tg * 2;
        float2 v0 = {acc_o[j][0] * il0, acc_o[j][1] * il0};
        float2 v1 = {acc_o[j][2] * il1, acc_o[j][3] * il1};
        *reinterpret_cast<float2*>(&g_att[row0 + col]) = v0;
        *reinterpret_cast<float2*>(&g_att[row1 + col]) = v1;
    }
}

// ---------------------------------------------------------------------------
// Launch
// ---------------------------------------------------------------------------
extern "C" void kernel_launch(void* const* d_in, const int* in_sizes, int n_in,
                              void* d_out, int out_size)
{
    const float* x           = (const float*)d_in[0];
    const int*   pad_mask    = (const int*)d_in[1];
    const float* alibi       = (const float*)d_in[2];
    const float* qkv_w       = (const float*)d_in[3];
    const float* proj_w      = (const float*)d_in[4];
    const float* proj_b      = (const float*)d_in[5];
    const float* logit_scale = (const float*)d_in[6];
    float*       out         = (float*)d_out;

    void *qkvp = nullptr, *attp = nullptr;
    cudaGetSymbolAddress(&qkvp, g_qkv);
    cudaGetSymbolAddress(&attp, g_att);

    // 1. qkv projection (tf32 mma, wide 128x128 tiles)
    gemm_mma_nt<<<dim3(THREEC / 128, MROWS / 128), 256>>>(
        x, qkv_w, nullptr, (float*)qkvp, MROWS, THREEC, Cc);

    // 2. normalize q and k head-rows in place
    norm_qk<<<(MROWS * 2 * Hh) / 8, 256>>>((float*)qkvp);

    // 3-5. fused scores + softmax + PV (round-11 proven version)
    attn_fused<<<dim3(Nn / 64, Bb * Hh), 128>>>(alibi, pad_mask, logit_scale);

    // 6. output projection + bias (tf32 mma, wide 128x128 tiles)
    gemm_mma_nt<<<dim3(Cc / 128, MROWS / 128), 256>>>(
        (const float*)attp, proj_w, proj_b, out, MROWS, Cc, Cc);
}